// round 13
// baseline (speedup 1.0000x reference)
#include <cuda_runtime.h>
#include <cuda_bf16.h>
#include <cuda_fp16.h>
#include <math.h>
#include <stdint.h>

#define NN 100000
#define EE 500000
#define D  128
#define HH 8
#define DKH 16

// ===================== scratch ==============================================
// edge-phase node features in fp16 (only consumer is aggr_kernel)
__device__ __half g_Pa_h[(size_t)NN * 640];   // [K_r0 | V_r0 | K_r2 | V_r2 | Q_a]
__device__ __half g_Pb_h[(size_t)NN * 384];   // [K_r1 | V_r1 | Q_b]
__device__ float g_t[2][(size_t)NN * D];      // 0: t_a (rel1), 1: t_b (rel0+2, normalized)
#define WT_ROWS (640 + 384 + 128 + 128)       // 1280
__device__ __nv_bfloat16 g_WtHi[WT_ROWS * D]; // W^T pre-split, [n][k]
__device__ __nv_bfloat16 g_WtLo[WT_ROWS * D];
__device__ float g_bias[WT_ROWS];
// CSR scratch
__device__ int g_deg[3][NN];
__device__ int g_off[3][NN];
__device__ int g_cur[3][NN];
__device__ int g_sid[3][EE];
__device__ int g_base[3];

// ---------------- helpers ----------------------------------------------------
__device__ __forceinline__ void split2(float x, float y, uint32_t& hi, uint32_t& lo) {
    __nv_bfloat16 hx = __float2bfloat16(x), hy = __float2bfloat16(y);
    __nv_bfloat16 lx = __float2bfloat16(x - __bfloat162float(hx));
    __nv_bfloat16 ly = __float2bfloat16(y - __bfloat162float(hy));
    hi = ((uint32_t)*(uint16_t*)&hy << 16) | *(uint16_t*)&hx;
    lo = ((uint32_t)*(uint16_t*)&ly << 16) | *(uint16_t*)&lx;
}
__device__ __forceinline__ void mma_bf16(float* c, const uint32_t* a, const uint32_t* b) {
    asm volatile("mma.sync.aligned.m16n8k16.row.col.f32.bf16.bf16.f32 "
                 "{%0,%1,%2,%3},{%4,%5,%6,%7},{%8,%9},{%0,%1,%2,%3};"
                 : "+f"(c[0]), "+f"(c[1]), "+f"(c[2]), "+f"(c[3])
                 : "r"(a[0]), "r"(a[1]), "r"(a[2]), "r"(a[3]), "r"(b[0]), "r"(b[1]));
}
__device__ __forceinline__ void loadf8(const __half* p, float* f) {
    uint4 q = *(const uint4*)p;
    const __half2* h = (const __half2*)&q;
    #pragma unroll
    for (int j = 0; j < 4; j++) {
        float2 t = __half22float2(h[j]);
        f[j * 2 + 0] = t.x;
        f[j * 2 + 1] = t.y;
    }
}

// ---------------- zero CSR counters each launch ------------------------------
__global__ void zero_kernel() {
    int idx = blockIdx.x * blockDim.x + threadIdx.x;
    int* dp = &g_deg[0][0];
    if (idx < 3 * NN) dp[idx] = 0;
    if (idx < 3) g_base[idx] = 0;
}

// ---------------- build transposed, relation-folded, bf16-split weights -----
__global__ void wcat_kernel(const float* __restrict__ Wk, const float* __restrict__ bk,
                            const float* __restrict__ Wv, const float* __restrict__ bv,
                            const float* __restrict__ Wq, const float* __restrict__ bq,
                            const float* __restrict__ Wa, const float* __restrict__ ba,
                            const float* __restrict__ rel_att, const float* __restrict__ rel_msg) {
    int idx = blockIdx.x * blockDim.x + threadIdx.x;
    if (idx >= WT_ROWS * D) return;
    int u = idx / D;      // output column n (transposed row)
    int k = idx % D;      // input dim
    float val = 0.f, bval = 0.f;
    if (u >= 1024) {      // out-proj GEMMs: plain Wa transpose
        int which = (u >= 1152) ? 1 : 0;
        int n = u - 1024 - which * 128;
        val  = Wa[which * D * D + k * D + n];
        bval = ba[which * D + n];
    } else {
        int o, tsrc;
        if (u < 640) { o = u;       tsrc = 0; }
        else         { o = u - 640; tsrc = 1; }
        int seg = o >> 7, oo = o & 127;
        bool isQ = (tsrc == 0) ? (seg == 4) : (seg == 2);
        if (isQ) {
            val  = Wq[tsrc * D * D + k * D + oo];
            bval = bq[tsrc * D + oo];
        } else {
            int r; bool isV;
            if (tsrc == 0) { r = (seg < 2) ? 0 : 2; isV = (seg & 1); }
            else           { r = 1; isV = (seg == 1); }
            const float* Wm  = isV ? Wv : Wk;
            const float* bm  = isV ? bv : bk;
            const float* rel = isV ? rel_msg : rel_att;
            int h = oo >> 4, e = oo & 15;
            const float* wrow = Wm + tsrc * D * D + k * D + h * DKH;
            const float* brow = bm + tsrc * D + h * DKH;
            const float* relm = rel + (r * HH + h) * DKH * DKH;
            float s = 0.f, sb = 0.f;
            #pragma unroll
            for (int d2 = 0; d2 < DKH; d2++) {
                float rv = relm[d2 * DKH + e];
                s  += wrow[d2] * rv;
                sb += brow[d2] * rv;
            }
            val = s; bval = sb;
        }
    }
    __nv_bfloat16 hi = __float2bfloat16(val);
    g_WtHi[u * D + k] = hi;
    g_WtLo[u * D + k] = __float2bfloat16(val - __bfloat162float(hi));
    if (k == 0) g_bias[u] = bval;
}

// ===================== CSR build ============================================
__global__ void hist_kernel(const int* __restrict__ d0, const int* __restrict__ d1,
                            const int* __restrict__ d2) {
    int idx = blockIdx.x * blockDim.x + threadIdx.x;
    if (idx >= 3 * EE) return;
    int r = idx / EE, e = idx - r * EE;
    const int* dp = (r == 0) ? d0 : (r == 1) ? d1 : d2;
    atomicAdd(&g_deg[r][dp[e]], 1);
}

__global__ void scan_kernel() {   // grid (98, 3), block 1024
    __shared__ int sh[1024];
    __shared__ int sbase;
    int r = blockIdx.y, tid = threadIdx.x;
    int i = blockIdx.x * 1024 + tid;
    int v = (i < NN) ? g_deg[r][i] : 0;
    sh[tid] = v;
    __syncthreads();
    for (int s = 1; s < 1024; s <<= 1) {
        int t = (tid >= s) ? sh[tid - s] : 0;
        __syncthreads();
        sh[tid] += t;
        __syncthreads();
    }
    if (tid == 1023) sbase = atomicAdd(&g_base[r], sh[1023]);
    __syncthreads();
    int off = sbase + sh[tid] - v;
    if (i < NN) { g_off[r][i] = off; g_cur[r][i] = off; }
}

__global__ void fill_kernel(const int* __restrict__ s0, const int* __restrict__ d0,
                            const int* __restrict__ s1, const int* __restrict__ d1,
                            const int* __restrict__ s2, const int* __restrict__ d2) {
    int idx = blockIdx.x * blockDim.x + threadIdx.x;
    if (idx >= 3 * EE) return;
    int r = idx / EE, e = idx - r * EE;
    const int* sp = (r == 0) ? s0 : (r == 1) ? s1 : s2;
    const int* dp = (r == 0) ? d0 : (r == 1) ? d1 : d2;
    int pos = atomicAdd(&g_cur[r][dp[e]], 1);
    g_sid[r][pos] = sp[e];
}

// ===================== dst-major edge aggregation (4 edges/warp) ============
// 8 lanes per edge; each lane owns one head (16 fp16 channels = 32 bytes).
// No shuffles inside the edge loop; cross-edge-group combine once per relation.
__device__ __forceinline__ void edge_loop4(const int* __restrict__ sp, int deg,
    const __half* __restrict__ kbase, int stride,
    const float* q16, float pri, int lane, float* acc, float& den)
{
    int sub = lane & 7, eg = lane >> 3;
    int iters = (deg + 3) >> 2;
    for (int it = 0; it < iters; it++) {
        int i = eg + 4 * it;
        bool valid = i < deg;
        int ic = valid ? i : deg - 1;
        int s = sp[ic];
        const __half* row = kbase + (size_t)s * stride + sub * 16;
        float k16[16];
        loadf8(row, k16);
        loadf8(row + 8, k16 + 8);
        float dot = 0.f;
        #pragma unroll
        for (int j = 0; j < 16; j++) dot += k16[j] * q16[j];
        float ex = valid ? __expf(dot * pri) : 0.f;
        float v16[16];
        loadf8(row + 128, v16);
        loadf8(row + 136, v16 + 8);
        #pragma unroll
        for (int j = 0; j < 16; j++) acc[j] += v16[j] * ex;
        den += ex;
    }
    // combine the 4 edge-groups
    #pragma unroll
    for (int j = 0; j < 16; j++) {
        acc[j] += __shfl_xor_sync(0xffffffffu, acc[j], 8);
        acc[j] += __shfl_xor_sync(0xffffffffu, acc[j], 16);
    }
    den += __shfl_xor_sync(0xffffffffu, den, 8);
    den += __shfl_xor_sync(0xffffffffu, den, 16);
}

// one warp per (group, dst). group 0: rel1 -> t_a. group 1: rel0+rel2 -> t_b
__global__ void aggr_kernel(const float* __restrict__ rel_pri) {
    int gw = (blockIdx.x * blockDim.x + threadIdx.x) >> 5;
    if (gw >= 2 * NN) return;
    int grp = gw / NN, d = gw - grp * NN;
    int lane = threadIdx.x & 31, sub = lane & 7;

    float q16[16], outv[16];
    if (grp == 0) {
        loadf8(g_Pa_h + (size_t)d * 640 + 512 + sub * 16, q16);
        loadf8(g_Pa_h + (size_t)d * 640 + 520 + sub * 16, q16 + 8);
        float acc[16] = {};
        float den = 0.f;
        edge_loop4(g_sid[1] + g_off[1][d], g_deg[1][d], g_Pb_h, 384, q16,
                   rel_pri[HH + sub] * 0.25f, lane, acc, den);
        float dn = (den > 0.f) ? (1.f / den) : 0.f;
        #pragma unroll
        for (int j = 0; j < 16; j++) outv[j] = acc[j] * dn;
    } else {
        loadf8(g_Pb_h + (size_t)d * 384 + 256 + sub * 16, q16);
        loadf8(g_Pb_h + (size_t)d * 384 + 264 + sub * 16, q16 + 8);
        float acc[16] = {};
        float den = 0.f;
        edge_loop4(g_sid[0] + g_off[0][d], g_deg[0][d], g_Pa_h, 640, q16,
                   rel_pri[sub] * 0.25f, lane, acc, den);
        float s0 = (den > 0.f) ? (0.5f / den) : 0.f;
        #pragma unroll
        for (int j = 0; j < 16; j++) { outv[j] = acc[j] * s0; acc[j] = 0.f; }
        den = 0.f;
        edge_loop4(g_sid[2] + g_off[2][d], g_deg[2][d], g_Pa_h + 256, 640, q16,
                   rel_pri[2 * HH + sub] * 0.25f, lane, acc, den);
        float s2 = (den > 0.f) ? (0.5f / den) : 0.f;
        #pragma unroll
        for (int j = 0; j < 16; j++) outv[j] += acc[j] * s2;
    }
    if (lane < 8) {
        float* tp = g_t[grp] + (size_t)d * D + sub * 16;
        #pragma unroll
        for (int j = 0; j < 4; j++)
            *(float4*)(tp + j * 4) = make_float4(outv[j * 4], outv[j * 4 + 1],
                                                 outv[j * 4 + 2], outv[j * 4 + 3]);
    }
}

// ===================== A-stationary bf16x3 mma.sync GEMM ====================
// mode 1 (proj): by 0/1 -> Pa_h tiles 0-4/5-9 (A=h_a); by 2 -> Pb_h tiles 0-5
//   (A=h_b). Epilogue converts to fp16.
// mode 2 (out): by=which, A=g_t[by], fp32 out with skip-mix epilogue.
#define AS_STRIDE 68
#define AS_PLANE  (128 * AS_STRIDE)            // 8704 words
#define BS_OFF    (2 * AS_PLANE)               // 17408
#define BS_PLANE  (64 * AS_STRIDE)             // 4352
#define SMEM_WORDS (BS_OFF + 2 * BS_PLANE)     // 26112 words = 104448 B

__global__ void __launch_bounds__(256) gemm10(
    int mode, const float* __restrict__ ha, const float* __restrict__ hb,
    const float* __restrict__ skipv, float* __restrict__ out)
{
    extern __shared__ uint32_t sm[];
    int by = blockIdx.y;
    const float* Asrc; int wtRow, cStride, nt0, nNT, skipIdx = 0;
    __half* Ch = nullptr;
    float* Cf = nullptr;
    const float* resid = nullptr;
    if (mode == 1) {
        if (by == 0)      { Asrc = ha; wtRow = 0;   Ch = g_Pa_h; cStride = 640; nt0 = 0; nNT = 5; }
        else if (by == 1) { Asrc = ha; wtRow = 0;   Ch = g_Pa_h; cStride = 640; nt0 = 5; nNT = 5; }
        else              { Asrc = hb; wtRow = 640; Ch = g_Pb_h; cStride = 384; nt0 = 0; nNT = 6; }
    } else {
        Asrc = g_t[by]; wtRow = 1024 + by * 128; Cf = out + (size_t)by * NN * D;
        cStride = 128; nt0 = 0; nNT = 2;
        resid = by ? hb : ha; skipIdx = by;
    }
    int biasOff = wtRow;

    int tid = threadIdx.x, lane = tid & 31, wid = tid >> 5;
    int warp_m = wid >> 1, warp_n = wid & 1;
    int g = lane >> 2, tg = lane & 3;
    int m0 = blockIdx.x * 128;
    const int M = NN;

    // ---- load A tile once (fp32 -> split planes) ----
    #pragma unroll
    for (int u = 0; u < 16; u++) {
        int flat = u * 256 + tid;          // 0..4095 float4 slots
        int row = flat >> 5, part = flat & 31;
        int grow = m0 + row;
        float4 v = make_float4(0.f, 0.f, 0.f, 0.f);
        if (grow < M) v = *(const float4*)(Asrc + ((size_t)grow << 7) + part * 4);
        uint32_t h01, l01, h23, l23;
        split2(v.x, v.y, h01, l01);
        split2(v.z, v.w, h23, l23);
        *(uint2*)&sm[row * AS_STRIDE + part * 2]            = make_uint2(h01, h23);
        *(uint2*)&sm[AS_PLANE + row * AS_STRIDE + part * 2] = make_uint2(l01, l23);
    }
    __syncthreads();

    float alpha = 1.f, om = 0.f;
    if (resid) {
        float s = skipv[skipIdx];
        alpha = 1.f / (1.f + expf(-s));
        om = 1.f - alpha;
    }

    for (int nt = nt0; nt < nt0 + nNT; nt++) {
        int n0 = nt * 64;
        // ---- load B tile (pre-split bf16, L2-resident) ----
        #pragma unroll
        for (int u = 0; u < 8; u++) {
            int flat = u * 256 + tid;          // 0..2047 uint4 slots
            int plane = flat >> 10;
            int rem = flat & 1023;
            int row = rem >> 4, part = rem & 15;
            const __nv_bfloat16* src = (plane ? g_WtLo : g_WtHi)
                + (size_t)(wtRow + n0 + row) * D + part * 8;
            *(uint4*)&sm[BS_OFF + plane * BS_PLANE + row * AS_STRIDE + part * 4] = *(const uint4*)src;
        }
        __syncthreads();

        float acc[2][4][4];
        #pragma unroll
        for (int mt = 0; mt < 2; mt++)
            #pragma unroll
            for (int ntt = 0; ntt < 4; ntt++)
                #pragma unroll
                for (int i = 0; i < 4; i++) acc[mt][ntt][i] = 0.f;

        #pragma unroll
        for (int kk = 0; kk < 8; kk++) {
            int kp0 = kk * 8;
            uint32_t ah[2][4], al[2][4], bh[4][2], bl[4][2];
            #pragma unroll
            for (int mt = 0; mt < 2; mt++) {
                int rb = warp_m * 32 + mt * 16;
                const uint32_t* A0 = sm;
                const uint32_t* A1 = sm + AS_PLANE;
                ah[mt][0] = A0[(rb + g) * AS_STRIDE + kp0 + tg];
                ah[mt][1] = A0[(rb + g + 8) * AS_STRIDE + kp0 + tg];
                ah[mt][2] = A0[(rb + g) * AS_STRIDE + kp0 + tg + 4];
                ah[mt][3] = A0[(rb + g + 8) * AS_STRIDE + kp0 + tg + 4];
                al[mt][0] = A1[(rb + g) * AS_STRIDE + kp0 + tg];
                al[mt][1] = A1[(rb + g + 8) * AS_STRIDE + kp0 + tg];
                al[mt][2] = A1[(rb + g) * AS_STRIDE + kp0 + tg + 4];
                al[mt][3] = A1[(rb + g + 8) * AS_STRIDE + kp0 + tg + 4];
            }
            #pragma unroll
            for (int ntt = 0; ntt < 4; ntt++) {
                int cb = warp_n * 32 + ntt * 8;
                const uint32_t* B0 = sm + BS_OFF;
                const uint32_t* B1 = sm + BS_OFF + BS_PLANE;
                bh[ntt][0] = B0[(cb + g) * AS_STRIDE + kp0 + tg];
                bh[ntt][1] = B0[(cb + g) * AS_STRIDE + kp0 + tg + 4];
                bl[ntt][0] = B1[(cb + g) * AS_STRIDE + kp0 + tg];
                bl[ntt][1] = B1[(cb + g) * AS_STRIDE + kp0 + tg + 4];
            }
            #pragma unroll
            for (int mt = 0; mt < 2; mt++)
                #pragma unroll
                for (int ntt = 0; ntt < 4; ntt++) {
                    mma_bf16(acc[mt][ntt], ah[mt], bh[ntt]);
                    mma_bf16(acc[mt][ntt], al[mt], bh[ntt]);
                    mma_bf16(acc[mt][ntt], ah[mt], bl[ntt]);
                }
        }
        __syncthreads();   // all warps done reading Bs before next tile load

        // ---- epilogue for this N-tile ----
        #pragma unroll
        for (int mt = 0; mt < 2; mt++)
            #pragma unroll
            for (int ntt = 0; ntt < 4; ntt++) {
                int col = n0 + warp_n * 32 + ntt * 8 + tg * 2;
                float b0 = g_bias[biasOff + col], b1 = g_bias[biasOff + col + 1];
                #pragma unroll
                for (int half = 0; half < 2; half++) {
                    int row = m0 + warp_m * 32 + mt * 16 + g + half * 8;
                    if (row >= M) continue;
                    float v0 = acc[mt][ntt][half * 2 + 0] + b0;
                    float v1 = acc[mt][ntt][half * 2 + 1] + b1;
                    if (mode == 1) {
                        *(__half2*)(Ch + (size_t)row * cStride + col) = __floats2half2_rn(v0, v1);
                    } else {
                        v0 = v0 * alpha + resid[(size_t)row * D + col] * om;
                        v1 = v1 * alpha + resid[(size_t)row * D + col + 1] * om;
                        *(float2*)(Cf + (size_t)row * cStride + col) = make_float2(v0, v1);
                    }
                }
            }
    }
}

// ---------------- launch ----------------------------------------------------
extern "C" void kernel_launch(void* const* d_in, const int* in_sizes, int n_in,
                              void* d_out, int out_size) {
    const float* h_a = (const float*)d_in[0];
    const float* h_b = (const float*)d_in[1];
    const int* src0 = (const int*)d_in[2]; const int* dst0 = (const int*)d_in[3];
    const int* src1 = (const int*)d_in[4]; const int* dst1 = (const int*)d_in[5];
    const int* src2 = (const int*)d_in[6]; const int* dst2 = (const int*)d_in[7];
    const float* Wk = (const float*)d_in[8];  const float* bk = (const float*)d_in[9];
    const float* Wv = (const float*)d_in[10]; const float* bv = (const float*)d_in[11];
    const float* Wq = (const float*)d_in[12]; const float* bq = (const float*)d_in[13];
    const float* Wa = (const float*)d_in[14]; const float* ba = (const float*)d_in[15];
    const float* rel_att = (const float*)d_in[16];
    const float* rel_msg = (const float*)d_in[17];
    const float* rel_pri = (const float*)d_in[18];
    const float* skip    = (const float*)d_in[19];
    float* out = (float*)d_out;

    static cudaStream_t s2 = nullptr;
    static cudaEvent_t evFork = nullptr, evJoin = nullptr;
    if (s2 == nullptr) {
        cudaStreamCreateWithFlags(&s2, cudaStreamNonBlocking);
        cudaEventCreateWithFlags(&evFork, cudaEventDisableTiming);
        cudaEventCreateWithFlags(&evJoin, cudaEventDisableTiming);
    }

    const int SMEM_BYTES = SMEM_WORDS * 4;   // 104448
    cudaFuncSetAttribute(gemm10, cudaFuncAttributeMaxDynamicSharedMemorySize, SMEM_BYTES);

    // fork: CSR build on side stream, overlapped with weight prep + proj GEMM
    cudaEventRecord(evFork, 0);
    cudaStreamWaitEvent(s2, evFork, 0);
    zero_kernel<<<(3 * NN + 255) / 256, 256, 0, s2>>>();
    hist_kernel<<<(3 * EE + 255) / 256, 256, 0, s2>>>(dst0, dst1, dst2);
    scan_kernel<<<dim3((NN + 1023) / 1024, 3), 1024, 0, s2>>>();
    fill_kernel<<<(3 * EE + 255) / 256, 256, 0, s2>>>(src0, dst0, src1, dst1, src2, dst2);
    cudaEventRecord(evJoin, s2);

    // main stream: weights + projections
    wcat_kernel<<<(WT_ROWS * D + 255) / 256, 256>>>(Wk, bk, Wv, bv, Wq, bq, Wa, ba, rel_att, rel_msg);
    int gm = (NN + 127) / 128;   // 782
    gemm10<<<dim3(gm, 3), 256, SMEM_BYTES>>>(1, h_a, h_b, skip, out);

    // join: aggregation needs projections + CSR
    cudaStreamWaitEvent(0, evJoin, 0);
    aggr_kernel<<<(2 * NN * 32 + 255) / 256, 256>>>(rel_pri);

    // output projections with skip mixing
    gemm10<<<dim3(gm, 2), 256, SMEM_BYTES>>>(2, h_a, h_b, skip, out);
}

// round 14
// speedup vs baseline: 1.3040x; 1.3040x over previous
#include <cuda_runtime.h>
#include <cuda_bf16.h>
#include <cuda_fp16.h>
#include <math.h>
#include <stdint.h>

#define NN 100000
#define EE 500000
#define D  128
#define HH 8
#define DKH 16

// ===================== scratch ==============================================
__device__ __half g_Pa_h[(size_t)NN * 640];   // [K_r0 | V_r0 | K_r2 | V_r2 | Q_a]
__device__ __half g_Pb_h[(size_t)NN * 384];   // [K_r1 | V_r1 | Q_b]
__device__ float g_t[2][(size_t)NN * D];      // 0: t_a (rel1), 1: t_b (rel0+2, normalized)
#define WT_ROWS (640 + 384 + 128 + 128)       // 1280
__device__ __half        g_Wt16[1024 * D];    // proj W^T in fp16 (single-pass GEMM)
__device__ __nv_bfloat16 g_WtHi[WT_ROWS * D]; // out-proj W^T pre-split (rows 1024..1279 used)
__device__ __nv_bfloat16 g_WtLo[WT_ROWS * D];
__device__ float g_bias[WT_ROWS];
// CSR scratch
__device__ int g_deg[3][NN];
__device__ int g_off[3][NN];
__device__ int g_cur[3][NN];
__device__ int g_sid[3][EE];
__device__ int g_base[3];

// ---------------- helpers ----------------------------------------------------
__device__ __forceinline__ void split2(float x, float y, uint32_t& hi, uint32_t& lo) {
    __nv_bfloat16 hx = __float2bfloat16(x), hy = __float2bfloat16(y);
    __nv_bfloat16 lx = __float2bfloat16(x - __bfloat162float(hx));
    __nv_bfloat16 ly = __float2bfloat16(y - __bfloat162float(hy));
    hi = ((uint32_t)*(uint16_t*)&hy << 16) | *(uint16_t*)&hx;
    lo = ((uint32_t)*(uint16_t*)&ly << 16) | *(uint16_t*)&lx;
}
__device__ __forceinline__ void mma_bf16(float* c, const uint32_t* a, const uint32_t* b) {
    asm volatile("mma.sync.aligned.m16n8k16.row.col.f32.bf16.bf16.f32 "
                 "{%0,%1,%2,%3},{%4,%5,%6,%7},{%8,%9},{%0,%1,%2,%3};"
                 : "+f"(c[0]), "+f"(c[1]), "+f"(c[2]), "+f"(c[3])
                 : "r"(a[0]), "r"(a[1]), "r"(a[2]), "r"(a[3]), "r"(b[0]), "r"(b[1]));
}
__device__ __forceinline__ void mma_f16(float* c, const uint32_t* a, const uint32_t* b) {
    asm volatile("mma.sync.aligned.m16n8k16.row.col.f32.f16.f16.f32 "
                 "{%0,%1,%2,%3},{%4,%5,%6,%7},{%8,%9},{%0,%1,%2,%3};"
                 : "+f"(c[0]), "+f"(c[1]), "+f"(c[2]), "+f"(c[3])
                 : "r"(a[0]), "r"(a[1]), "r"(a[2]), "r"(a[3]), "r"(b[0]), "r"(b[1]));
}
__device__ __forceinline__ float4 load_h4(const __half* p) {
    uint2 q = *(const uint2*)p;
    float2 a = __half22float2(*(__half2*)&q.x);
    float2 b = __half22float2(*(__half2*)&q.y);
    return make_float4(a.x, a.y, b.x, b.y);
}

// ---------------- zero CSR counters each launch ------------------------------
__global__ void zero_kernel() {
    int idx = blockIdx.x * blockDim.x + threadIdx.x;
    int* dp = &g_deg[0][0];
    if (idx < 3 * NN) dp[idx] = 0;
    if (idx < 3) g_base[idx] = 0;
}

// ---------------- build transposed, relation-folded weights -----------------
__global__ void wcat_kernel(const float* __restrict__ Wk, const float* __restrict__ bk,
                            const float* __restrict__ Wv, const float* __restrict__ bv,
                            const float* __restrict__ Wq, const float* __restrict__ bq,
                            const float* __restrict__ Wa, const float* __restrict__ ba,
                            const float* __restrict__ rel_att, const float* __restrict__ rel_msg) {
    int idx = blockIdx.x * blockDim.x + threadIdx.x;
    if (idx >= WT_ROWS * D) return;
    int u = idx / D;      // output column n (transposed row)
    int k = idx % D;      // input dim
    float val = 0.f, bval = 0.f;
    if (u >= 1024) {      // out-proj GEMMs: plain Wa transpose
        int which = (u >= 1152) ? 1 : 0;
        int n = u - 1024 - which * 128;
        val  = Wa[which * D * D + k * D + n];
        bval = ba[which * D + n];
    } else {
        int o, tsrc;
        if (u < 640) { o = u;       tsrc = 0; }
        else         { o = u - 640; tsrc = 1; }
        int seg = o >> 7, oo = o & 127;
        bool isQ = (tsrc == 0) ? (seg == 4) : (seg == 2);
        if (isQ) {
            val  = Wq[tsrc * D * D + k * D + oo];
            bval = bq[tsrc * D + oo];
        } else {
            int r; bool isV;
            if (tsrc == 0) { r = (seg < 2) ? 0 : 2; isV = (seg & 1); }
            else           { r = 1; isV = (seg == 1); }
            const float* Wm  = isV ? Wv : Wk;
            const float* bm  = isV ? bv : bk;
            const float* rel = isV ? rel_msg : rel_att;
            int h = oo >> 4, e = oo & 15;
            const float* wrow = Wm + tsrc * D * D + k * D + h * DKH;
            const float* brow = bm + tsrc * D + h * DKH;
            const float* relm = rel + (r * HH + h) * DKH * DKH;
            float s = 0.f, sb = 0.f;
            #pragma unroll
            for (int d2 = 0; d2 < DKH; d2++) {
                float rv = relm[d2 * DKH + e];
                s  += wrow[d2] * rv;
                sb += brow[d2] * rv;
            }
            val = s; bval = sb;
        }
    }
    if (u < 1024) {
        g_Wt16[u * D + k] = __float2half(val);
    } else {
        __nv_bfloat16 hi = __float2bfloat16(val);
        g_WtHi[u * D + k] = hi;
        g_WtLo[u * D + k] = __float2bfloat16(val - __bfloat162float(hi));
    }
    if (k == 0) g_bias[u] = bval;
}

// ===================== CSR build ============================================
__global__ void hist_kernel(const int* __restrict__ d0, const int* __restrict__ d1,
                            const int* __restrict__ d2) {
    int idx = blockIdx.x * blockDim.x + threadIdx.x;
    if (idx >= 3 * EE) return;
    int r = idx / EE, e = idx - r * EE;
    const int* dp = (r == 0) ? d0 : (r == 1) ? d1 : d2;
    atomicAdd(&g_deg[r][dp[e]], 1);
}

__global__ void scan_kernel() {   // grid (98, 3), block 1024
    __shared__ int sh[1024];
    __shared__ int sbase;
    int r = blockIdx.y, tid = threadIdx.x;
    int i = blockIdx.x * 1024 + tid;
    int v = (i < NN) ? g_deg[r][i] : 0;
    sh[tid] = v;
    __syncthreads();
    for (int s = 1; s < 1024; s <<= 1) {
        int t = (tid >= s) ? sh[tid - s] : 0;
        __syncthreads();
        sh[tid] += t;
        __syncthreads();
    }
    if (tid == 1023) sbase = atomicAdd(&g_base[r], sh[1023]);
    __syncthreads();
    int off = sbase + sh[tid] - v;
    if (i < NN) { g_off[r][i] = off; g_cur[r][i] = off; }
}

__global__ void fill_kernel(const int* __restrict__ s0, const int* __restrict__ d0,
                            const int* __restrict__ s1, const int* __restrict__ d1,
                            const int* __restrict__ s2, const int* __restrict__ d2) {
    int idx = blockIdx.x * blockDim.x + threadIdx.x;
    if (idx >= 3 * EE) return;
    int r = idx / EE, e = idx - r * EE;
    const int* sp = (r == 0) ? s0 : (r == 1) ? s1 : s2;
    const int* dp = (r == 0) ? d0 : (r == 1) ? d1 : d2;
    int pos = atomicAdd(&g_cur[r][dp[e]], 1);
    g_sid[r][pos] = sp[e];
}

// ===================== dst-major edge aggregation (R11 version) =============
__device__ __forceinline__ void edge_loop(const int* __restrict__ sp, int deg,
    const __half* __restrict__ base, int stride, float4 qv, float pri, int lane,
    float4& acc, float& den)
{
    for (int i0 = 0; i0 < deg; i0 += 32) {
        int n = deg - i0; if (n > 32) n = 32;
        int sid = (lane < n) ? sp[i0 + lane] : 0;
        for (int i = 0; i < n; i++) {
            int s = __shfl_sync(0xffffffffu, sid, i);
            const __half* row = base + (size_t)s * stride;
            float4 kv = load_h4(row + lane * 4);
            float dot = kv.x * qv.x + kv.y * qv.y + kv.z * qv.z + kv.w * qv.w;
            dot += __shfl_xor_sync(0xffffffffu, dot, 1);
            dot += __shfl_xor_sync(0xffffffffu, dot, 2);
            float ex = expf(dot * pri);
            float4 vv = load_h4(row + 128 + lane * 4);
            acc.x += vv.x * ex; acc.y += vv.y * ex;
            acc.z += vv.z * ex; acc.w += vv.w * ex;
            den += ex;
        }
    }
}

// one warp per (group, dst). group 0: rel1 -> t_a. group 1: rel0+rel2 -> t_b
__global__ void aggr_kernel(const float* __restrict__ rel_pri) {
    int gw = (blockIdx.x * blockDim.x + threadIdx.x) >> 5;
    if (gw >= 2 * NN) return;
    int grp = gw / NN, d = gw - grp * NN;
    int lane = threadIdx.x & 31, h = lane >> 2;
    float4 outv;
    if (grp == 0) {
        float4 qv = load_h4(g_Pa_h + (size_t)d * 640 + 512 + lane * 4);
        float pri = rel_pri[HH + h] * 0.25f;   // / sqrt(16)
        float4 acc = make_float4(0.f, 0.f, 0.f, 0.f);
        float den = 0.f;
        edge_loop(g_sid[1] + g_off[1][d], g_deg[1][d], g_Pb_h, 384, qv, pri, lane, acc, den);
        float dn = (den > 0.f) ? (1.f / den) : 0.f;
        outv = make_float4(acc.x * dn, acc.y * dn, acc.z * dn, acc.w * dn);
    } else {
        float4 qv = load_h4(g_Pb_h + (size_t)d * 384 + 256 + lane * 4);
        float4 a0 = make_float4(0.f, 0.f, 0.f, 0.f), a2 = make_float4(0.f, 0.f, 0.f, 0.f);
        float den0 = 0.f, den2 = 0.f;
        edge_loop(g_sid[0] + g_off[0][d], g_deg[0][d], g_Pa_h,       640, qv,
                  rel_pri[h] * 0.25f, lane, a0, den0);
        edge_loop(g_sid[2] + g_off[2][d], g_deg[2][d], g_Pa_h + 256, 640, qv,
                  rel_pri[2 * HH + h] * 0.25f, lane, a2, den2);
        float s0 = (den0 > 0.f) ? (0.5f / den0) : 0.f;
        float s2 = (den2 > 0.f) ? (0.5f / den2) : 0.f;
        outv = make_float4(a0.x * s0 + a2.x * s2, a0.y * s0 + a2.y * s2,
                           a0.z * s0 + a2.z * s2, a0.w * s0 + a2.w * s2);
    }
    *(float4*)(g_t[grp] + (size_t)d * D + lane * 4) = outv;
}

// ===================== single-pass fp16 projection GEMM =====================
// A tile (128 rows, K=128 fp16) resident; loop N-tiles. Output fp16.
#define PAS 68                                    // words per row (conflict-free)
#define P_AS_WORDS (128 * PAS)                    // 8704
#define P_BS_WORDS (64 * PAS)                     // 4352
#define P_SMEM_BYTES ((P_AS_WORDS + P_BS_WORDS) * 4)   // 52224

__global__ void __launch_bounds__(256) gemm_proj(
    const float* __restrict__ ha, const float* __restrict__ hb)
{
    extern __shared__ uint32_t sm[];
    uint32_t* As = sm;
    uint32_t* Bs = sm + P_AS_WORDS;
    int by = blockIdx.y;
    const float* Asrc; int wtRow, cStride, nt0, nNT;
    __half* C;
    if (by == 0)      { Asrc = ha; wtRow = 0;   C = g_Pa_h; cStride = 640; nt0 = 0; nNT = 5; }
    else if (by == 1) { Asrc = ha; wtRow = 0;   C = g_Pa_h; cStride = 640; nt0 = 5; nNT = 5; }
    else              { Asrc = hb; wtRow = 640; C = g_Pb_h; cStride = 384; nt0 = 0; nNT = 6; }
    int biasOff = wtRow;

    int tid = threadIdx.x, lane = tid & 31, wid = tid >> 5;
    int warp_m = wid >> 1, warp_n = wid & 1;
    int g = lane >> 2, tg = lane & 3;
    int m0 = blockIdx.x * 128;
    const int M = NN;

    // ---- load A tile once (fp32 -> fp16) ----
    #pragma unroll
    for (int u = 0; u < 16; u++) {
        int flat = u * 256 + tid;          // 0..4095 float4 slots
        int row = flat >> 5, part = flat & 31;
        int grow = m0 + row;
        float4 v = make_float4(0.f, 0.f, 0.f, 0.f);
        if (grow < M) v = *(const float4*)(Asrc + ((size_t)grow << 7) + part * 4);
        uint32_t p01 = __half2_raw(__floats2half2_rn(v.x, v.y)).x
                     | ((uint32_t)__half2_raw(__floats2half2_rn(v.x, v.y)).y << 16);
        // simpler: build via union
        __half2 h01 = __floats2half2_rn(v.x, v.y);
        __half2 h23 = __floats2half2_rn(v.z, v.w);
        uint32_t w0 = *(uint32_t*)&h01, w1 = *(uint32_t*)&h23;
        (void)p01;
        *(uint2*)&As[row * PAS + part * 2] = make_uint2(w0, w1);
    }
    __syncthreads();

    for (int nt = nt0; nt < nt0 + nNT; nt++) {
        int n0 = nt * 64;
        // ---- load B tile (fp16, L2-resident) ----
        #pragma unroll
        for (int u = 0; u < 4; u++) {
            int flat = u * 256 + tid;          // 0..1023 uint4 slots
            int row = flat >> 4, part = flat & 15;
            const __half* src = g_Wt16 + (size_t)(wtRow + n0 + row) * D + part * 8;
            *(uint4*)&Bs[row * PAS + part * 4] = *(const uint4*)src;
        }
        __syncthreads();

        float acc[2][4][4];
        #pragma unroll
        for (int mt = 0; mt < 2; mt++)
            #pragma unroll
            for (int ntt = 0; ntt < 4; ntt++)
                #pragma unroll
                for (int i = 0; i < 4; i++) acc[mt][ntt][i] = 0.f;

        #pragma unroll
        for (int kk = 0; kk < 8; kk++) {
            int kp0 = kk * 8;
            uint32_t a[2][4], b[4][2];
            #pragma unroll
            for (int mt = 0; mt < 2; mt++) {
                int rb = warp_m * 32 + mt * 16;
                a[mt][0] = As[(rb + g) * PAS + kp0 + tg];
                a[mt][1] = As[(rb + g + 8) * PAS + kp0 + tg];
                a[mt][2] = As[(rb + g) * PAS + kp0 + tg + 4];
                a[mt][3] = As[(rb + g + 8) * PAS + kp0 + tg + 4];
            }
            #pragma unroll
            for (int ntt = 0; ntt < 4; ntt++) {
                int cb = warp_n * 32 + ntt * 8;
                b[ntt][0] = Bs[(cb + g) * PAS + kp0 + tg];
                b[ntt][1] = Bs[(cb + g) * PAS + kp0 + tg + 4];
            }
            #pragma unroll
            for (int mt = 0; mt < 2; mt++)
                #pragma unroll
                for (int ntt = 0; ntt < 4; ntt++)
                    mma_f16(acc[mt][ntt], a[mt], b[ntt]);
        }
        __syncthreads();

        // ---- epilogue: bias + fp16 store ----
        #pragma unroll
        for (int mt = 0; mt < 2; mt++)
            #pragma unroll
            for (int ntt = 0; ntt < 4; ntt++) {
                int col = n0 + warp_n * 32 + ntt * 8 + tg * 2;
                float b0 = g_bias[biasOff + col], b1 = g_bias[biasOff + col + 1];
                #pragma unroll
                for (int half = 0; half < 2; half++) {
                    int row = m0 + warp_m * 32 + mt * 16 + g + half * 8;
                    if (row >= M) continue;
                    float v0 = acc[mt][ntt][half * 2 + 0] + b0;
                    float v1 = acc[mt][ntt][half * 2 + 1] + b1;
                    *(__half2*)(C + (size_t)row * cStride + col) = __floats2half2_rn(v0, v1);
                }
            }
    }
}

// ===================== bf16x3 output GEMM (A = g_t, skip-mix) ===============
#define AS_STRIDE 68
#define AS_PLANE  (128 * AS_STRIDE)            // 8704 words
#define BS_OFF    (2 * AS_PLANE)               // 17408
#define BS_PLANE  (64 * AS_STRIDE)             // 4352
#define SMEM_WORDS (BS_OFF + 2 * BS_PLANE)     // 26112 words = 104448 B

__global__ void __launch_bounds__(256) gemm_out(
    const float* __restrict__ ha, const float* __restrict__ hb,
    const float* __restrict__ skipv, float* __restrict__ out)
{
    extern __shared__ uint32_t sm[];
    int by = blockIdx.y;
    const float* Asrc = g_t[by];
    int wtRow = 1024 + by * 128;
    int biasOff = wtRow;
    float* Cf = out + (size_t)by * NN * D;
    const float* resid = by ? hb : ha;

    int tid = threadIdx.x, lane = tid & 31, wid = tid >> 5;
    int warp_m = wid >> 1, warp_n = wid & 1;
    int g = lane >> 2, tg = lane & 3;
    int m0 = blockIdx.x * 128;
    const int M = NN;

    #pragma unroll
    for (int u = 0; u < 16; u++) {
        int flat = u * 256 + tid;
        int row = flat >> 5, part = flat & 31;
        int grow = m0 + row;
        float4 v = make_float4(0.f, 0.f, 0.f, 0.f);
        if (grow < M) v = *(const float4*)(Asrc + ((size_t)grow << 7) + part * 4);
        uint32_t h01, l01, h23, l23;
        split2(v.x, v.y, h01, l01);
        split2(v.z, v.w, h23, l23);
        *(uint2*)&sm[row * AS_STRIDE + part * 2]            = make_uint2(h01, h23);
        *(uint2*)&sm[AS_PLANE + row * AS_STRIDE + part * 2] = make_uint2(l01, l23);
    }
    __syncthreads();

    float s = skipv[by];
    float alpha = 1.f / (1.f + expf(-s));
    float om = 1.f - alpha;

    for (int nt = 0; nt < 2; nt++) {
        int n0 = nt * 64;
        #pragma unroll
        for (int u = 0; u < 8; u++) {
            int flat = u * 256 + tid;
            int plane = flat >> 10;
            int rem = flat & 1023;
            int row = rem >> 4, part = rem & 15;
            const __nv_bfloat16* src = (plane ? g_WtLo : g_WtHi)
                + (size_t)(wtRow + n0 + row) * D + part * 8;
            *(uint4*)&sm[BS_OFF + plane * BS_PLANE + row * AS_STRIDE + part * 4] = *(const uint4*)src;
        }
        __syncthreads();

        float acc[2][4][4];
        #pragma unroll
        for (int mt = 0; mt < 2; mt++)
            #pragma unroll
            for (int ntt = 0; ntt < 4; ntt++)
                #pragma unroll
                for (int i = 0; i < 4; i++) acc[mt][ntt][i] = 0.f;

        #pragma unroll
        for (int kk = 0; kk < 8; kk++) {
            int kp0 = kk * 8;
            uint32_t ah[2][4], al[2][4], bh[4][2], bl[4][2];
            #pragma unroll
            for (int mt = 0; mt < 2; mt++) {
                int rb = warp_m * 32 + mt * 16;
                const uint32_t* A0 = sm;
                const uint32_t* A1 = sm + AS_PLANE;
                ah[mt][0] = A0[(rb + g) * AS_STRIDE + kp0 + tg];
                ah[mt][1] = A0[(rb + g + 8) * AS_STRIDE + kp0 + tg];
                ah[mt][2] = A0[(rb + g) * AS_STRIDE + kp0 + tg + 4];
                ah[mt][3] = A0[(rb + g + 8) * AS_STRIDE + kp0 + tg + 4];
                al[mt][0] = A1[(rb + g) * AS_STRIDE + kp0 + tg];
                al[mt][1] = A1[(rb + g + 8) * AS_STRIDE + kp0 + tg];
                al[mt][2] = A1[(rb + g) * AS_STRIDE + kp0 + tg + 4];
                al[mt][3] = A1[(rb + g + 8) * AS_STRIDE + kp0 + tg + 4];
            }
            #pragma unroll
            for (int ntt = 0; ntt < 4; ntt++) {
                int cb = warp_n * 32 + ntt * 8;
                const uint32_t* B0 = sm + BS_OFF;
                const uint32_t* B1 = sm + BS_OFF + BS_PLANE;
                bh[ntt][0] = B0[(cb + g) * AS_STRIDE + kp0 + tg];
                bh[ntt][1] = B0[(cb + g) * AS_STRIDE + kp0 + tg + 4];
                bl[ntt][0] = B1[(cb + g) * AS_STRIDE + kp0 + tg];
                bl[ntt][1] = B1[(cb + g) * AS_STRIDE + kp0 + tg + 4];
            }
            #pragma unroll
            for (int mt = 0; mt < 2; mt++)
                #pragma unroll
                for (int ntt = 0; ntt < 4; ntt++) {
                    mma_bf16(acc[mt][ntt], ah[mt], bh[ntt]);
                    mma_bf16(acc[mt][ntt], al[mt], bh[ntt]);
                    mma_bf16(acc[mt][ntt], ah[mt], bl[ntt]);
                }
        }
        __syncthreads();

        #pragma unroll
        for (int mt = 0; mt < 2; mt++)
            #pragma unroll
            for (int ntt = 0; ntt < 4; ntt++) {
                int col = n0 + warp_n * 32 + ntt * 8 + tg * 2;
                float b0 = g_bias[biasOff + col], b1 = g_bias[biasOff + col + 1];
                #pragma unroll
                for (int half = 0; half < 2; half++) {
                    int row = m0 + warp_m * 32 + mt * 16 + g + half * 8;
                    if (row >= M) continue;
                    float v0 = acc[mt][ntt][half * 2 + 0] + b0;
                    float v1 = acc[mt][ntt][half * 2 + 1] + b1;
                    v0 = v0 * alpha + resid[(size_t)row * D + col] * om;
                    v1 = v1 * alpha + resid[(size_t)row * D + col + 1] * om;
                    *(float2*)(Cf + (size_t)row * 128 + col) = make_float2(v0, v1);
                }
            }
    }
}

// ---------------- launch ----------------------------------------------------
extern "C" void kernel_launch(void* const* d_in, const int* in_sizes, int n_in,
                              void* d_out, int out_size) {
    const float* h_a = (const float*)d_in[0];
    const float* h_b = (const float*)d_in[1];
    const int* src0 = (const int*)d_in[2]; const int* dst0 = (const int*)d_in[3];
    const int* src1 = (const int*)d_in[4]; const int* dst1 = (const int*)d_in[5];
    const int* src2 = (const int*)d_in[6]; const int* dst2 = (const int*)d_in[7];
    const float* Wk = (const float*)d_in[8];  const float* bk = (const float*)d_in[9];
    const float* Wv = (const float*)d_in[10]; const float* bv = (const float*)d_in[11];
    const float* Wq = (const float*)d_in[12]; const float* bq = (const float*)d_in[13];
    const float* Wa = (const float*)d_in[14]; const float* ba = (const float*)d_in[15];
    const float* rel_att = (const float*)d_in[16];
    const float* rel_msg = (const float*)d_in[17];
    const float* rel_pri = (const float*)d_in[18];
    const float* skip    = (const float*)d_in[19];
    float* out = (float*)d_out;

    static cudaStream_t s2 = nullptr;
    static cudaEvent_t evFork = nullptr, evJoin = nullptr;
    if (s2 == nullptr) {
        cudaStreamCreateWithFlags(&s2, cudaStreamNonBlocking);
        cudaEventCreateWithFlags(&evFork, cudaEventDisableTiming);
        cudaEventCreateWithFlags(&evJoin, cudaEventDisableTiming);
    }

    cudaFuncSetAttribute(gemm_proj, cudaFuncAttributeMaxDynamicSharedMemorySize, P_SMEM_BYTES);
    cudaFuncSetAttribute(gemm_out,  cudaFuncAttributeMaxDynamicSharedMemorySize, SMEM_WORDS * 4);

    // fork: CSR build on side stream, overlapped with weight prep + proj GEMM
    cudaEventRecord(evFork, 0);
    cudaStreamWaitEvent(s2, evFork, 0);
    zero_kernel<<<(3 * NN + 255) / 256, 256, 0, s2>>>();
    hist_kernel<<<(3 * EE + 255) / 256, 256, 0, s2>>>(dst0, dst1, dst2);
    scan_kernel<<<dim3((NN + 1023) / 1024, 3), 1024, 0, s2>>>();
    fill_kernel<<<(3 * EE + 255) / 256, 256, 0, s2>>>(src0, dst0, src1, dst1, src2, dst2);
    cudaEventRecord(evJoin, s2);

    // main stream: weights + projections (single-pass fp16)
    wcat_kernel<<<(WT_ROWS * D + 255) / 256, 256>>>(Wk, bk, Wv, bv, Wq, bq, Wa, ba, rel_att, rel_msg);
    int gm = (NN + 127) / 128;   // 782
    gemm_proj<<<dim3(gm, 3), 256, P_SMEM_BYTES>>>(h_a, h_b);

    // join: aggregation needs projections + CSR
    cudaStreamWaitEvent(0, evJoin, 0);
    aggr_kernel<<<(2 * NN * 32 + 255) / 256, 256>>>(rel_pri);

    // output projections (bf16x3 accuracy) with skip mixing
    gemm_out<<<dim3(gm, 2), 256, SMEM_WORDS * 4>>>(h_a, h_b, skip, out);
}

// round 15
// speedup vs baseline: 1.3601x; 1.0430x over previous
#include <cuda_runtime.h>
#include <cuda_bf16.h>
#include <cuda_fp16.h>
#include <math.h>
#include <stdint.h>

#define NN 100000
#define EE 500000
#define D  128
#define HH 8
#define DKH 16

// ===================== scratch ==============================================
__device__ __half g_Pa_h[(size_t)NN * 640];   // [K_r0 | V_r0 | K_r2 | V_r2 | Q_a]
__device__ __half g_Pb_h[(size_t)NN * 384];   // [K_r1 | V_r1 | Q_b]
__device__ __half g_t_h[2][(size_t)NN * D];   // 0: t_a (rel1), 1: t_b (rel0+2, normalized)
#define WT_ROWS (640 + 384 + 128 + 128)       // 1280 (all fp16 now)
__device__ __half g_Wt16[WT_ROWS * D];        // W^T in fp16
__device__ float g_bias[WT_ROWS];
// CSR scratch
__device__ int g_deg[3][NN];
__device__ int g_off[3][NN];
__device__ int g_cur[3][NN];
__device__ int g_sid[3][EE];
__device__ int g_base[3];

// ---------------- helpers ----------------------------------------------------
__device__ __forceinline__ void mma_f16(float* c, const uint32_t* a, const uint32_t* b) {
    asm volatile("mma.sync.aligned.m16n8k16.row.col.f32.f16.f16.f32 "
                 "{%0,%1,%2,%3},{%4,%5,%6,%7},{%8,%9},{%0,%1,%2,%3};"
                 : "+f"(c[0]), "+f"(c[1]), "+f"(c[2]), "+f"(c[3])
                 : "r"(a[0]), "r"(a[1]), "r"(a[2]), "r"(a[3]), "r"(b[0]), "r"(b[1]));
}
__device__ __forceinline__ float4 load_h4(const __half* p) {
    uint2 q = *(const uint2*)p;
    float2 a = __half22float2(*(__half2*)&q.x);
    float2 b = __half22float2(*(__half2*)&q.y);
    return make_float4(a.x, a.y, b.x, b.y);
}

// ---------------- zero CSR counters each launch ------------------------------
__global__ void zero_kernel() {
    int idx = blockIdx.x * blockDim.x + threadIdx.x;
    int* dp = &g_deg[0][0];
    if (idx < 3 * NN) dp[idx] = 0;
    if (idx < 3) g_base[idx] = 0;
}

// ---------------- build transposed, relation-folded fp16 weights -------------
__global__ void wcat_kernel(const float* __restrict__ Wk, const float* __restrict__ bk,
                            const float* __restrict__ Wv, const float* __restrict__ bv,
                            const float* __restrict__ Wq, const float* __restrict__ bq,
                            const float* __restrict__ Wa, const float* __restrict__ ba,
                            const float* __restrict__ rel_att, const float* __restrict__ rel_msg) {
    int idx = blockIdx.x * blockDim.x + threadIdx.x;
    if (idx >= WT_ROWS * D) return;
    int u = idx / D;      // output column n (transposed row)
    int k = idx % D;      // input dim
    float val = 0.f, bval = 0.f;
    if (u >= 1024) {      // out-proj GEMMs: plain Wa transpose
        int which = (u >= 1152) ? 1 : 0;
        int n = u - 1024 - which * 128;
        val  = Wa[which * D * D + k * D + n];
        bval = ba[which * D + n];
    } else {
        int o, tsrc;
        if (u < 640) { o = u;       tsrc = 0; }
        else         { o = u - 640; tsrc = 1; }
        int seg = o >> 7, oo = o & 127;
        bool isQ = (tsrc == 0) ? (seg == 4) : (seg == 2);
        if (isQ) {
            val  = Wq[tsrc * D * D + k * D + oo];
            bval = bq[tsrc * D + oo];
        } else {
            int r; bool isV;
            if (tsrc == 0) { r = (seg < 2) ? 0 : 2; isV = (seg & 1); }
            else           { r = 1; isV = (seg == 1); }
            const float* Wm  = isV ? Wv : Wk;
            const float* bm  = isV ? bv : bk;
            const float* rel = isV ? rel_msg : rel_att;
            int h = oo >> 4, e = oo & 15;
            const float* wrow = Wm + tsrc * D * D + k * D + h * DKH;
            const float* brow = bm + tsrc * D + h * DKH;
            const float* relm = rel + (r * HH + h) * DKH * DKH;
            float s = 0.f, sb = 0.f;
            #pragma unroll
            for (int d2 = 0; d2 < DKH; d2++) {
                float rv = relm[d2 * DKH + e];
                s  += wrow[d2] * rv;
                sb += brow[d2] * rv;
            }
            val = s; bval = sb;
        }
    }
    g_Wt16[u * D + k] = __float2half(val);
    if (k == 0) g_bias[u] = bval;
}

// ===================== CSR build ============================================
__global__ void hist_kernel(const int* __restrict__ d0, const int* __restrict__ d1,
                            const int* __restrict__ d2) {
    int idx = blockIdx.x * blockDim.x + threadIdx.x;
    if (idx >= 3 * EE) return;
    int r = idx / EE, e = idx - r * EE;
    const int* dp = (r == 0) ? d0 : (r == 1) ? d1 : d2;
    atomicAdd(&g_deg[r][dp[e]], 1);
}

__global__ void scan_kernel() {   // grid (98, 3), block 1024
    __shared__ int sh[1024];
    __shared__ int sbase;
    int r = blockIdx.y, tid = threadIdx.x;
    int i = blockIdx.x * 1024 + tid;
    int v = (i < NN) ? g_deg[r][i] : 0;
    sh[tid] = v;
    __syncthreads();
    for (int s = 1; s < 1024; s <<= 1) {
        int t = (tid >= s) ? sh[tid - s] : 0;
        __syncthreads();
        sh[tid] += t;
        __syncthreads();
    }
    if (tid == 1023) sbase = atomicAdd(&g_base[r], sh[1023]);
    __syncthreads();
    int off = sbase + sh[tid] - v;
    if (i < NN) { g_off[r][i] = off; g_cur[r][i] = off; }
}

__global__ void fill_kernel(const int* __restrict__ s0, const int* __restrict__ d0,
                            const int* __restrict__ s1, const int* __restrict__ d1,
                            const int* __restrict__ s2, const int* __restrict__ d2) {
    int idx = blockIdx.x * blockDim.x + threadIdx.x;
    if (idx >= 3 * EE) return;
    int r = idx / EE, e = idx - r * EE;
    const int* sp = (r == 0) ? s0 : (r == 1) ? s1 : s2;
    const int* dp = (r == 0) ? d0 : (r == 1) ? d1 : d2;
    int pos = atomicAdd(&g_cur[r][dp[e]], 1);
    g_sid[r][pos] = sp[e];
}

// ===================== dst-major edge aggregation (R11 structure) ===========
__device__ __forceinline__ void edge_loop(const int* __restrict__ sp, int deg,
    const __half* __restrict__ base, int stride, float4 qv, float pri, int lane,
    float4& acc, float& den)
{
    for (int i0 = 0; i0 < deg; i0 += 32) {
        int n = deg - i0; if (n > 32) n = 32;
        int sid = (lane < n) ? sp[i0 + lane] : 0;
        for (int i = 0; i < n; i++) {
            int s = __shfl_sync(0xffffffffu, sid, i);
            const __half* row = base + (size_t)s * stride;
            float4 kv = load_h4(row + lane * 4);
            float dot = kv.x * qv.x + kv.y * qv.y + kv.z * qv.z + kv.w * qv.w;
            dot += __shfl_xor_sync(0xffffffffu, dot, 1);
            dot += __shfl_xor_sync(0xffffffffu, dot, 2);
            float ex = expf(dot * pri);
            float4 vv = load_h4(row + 128 + lane * 4);
            acc.x += vv.x * ex; acc.y += vv.y * ex;
            acc.z += vv.z * ex; acc.w += vv.w * ex;
            den += ex;
        }
    }
}

// one warp per (group, dst). group 0: rel1 -> t_a. group 1: rel0+rel2 -> t_b
__global__ void aggr_kernel(const float* __restrict__ rel_pri) {
    int gw = (blockIdx.x * blockDim.x + threadIdx.x) >> 5;
    if (gw >= 2 * NN) return;
    int grp = gw / NN, d = gw - grp * NN;
    int lane = threadIdx.x & 31, h = lane >> 2;
    float4 outv;
    if (grp == 0) {
        float4 qv = load_h4(g_Pa_h + (size_t)d * 640 + 512 + lane * 4);
        float pri = rel_pri[HH + h] * 0.25f;   // / sqrt(16)
        float4 acc = make_float4(0.f, 0.f, 0.f, 0.f);
        float den = 0.f;
        edge_loop(g_sid[1] + g_off[1][d], g_deg[1][d], g_Pb_h, 384, qv, pri, lane, acc, den);
        float dn = (den > 0.f) ? (1.f / den) : 0.f;
        outv = make_float4(acc.x * dn, acc.y * dn, acc.z * dn, acc.w * dn);
    } else {
        float4 qv = load_h4(g_Pb_h + (size_t)d * 384 + 256 + lane * 4);
        float4 a0 = make_float4(0.f, 0.f, 0.f, 0.f), a2 = make_float4(0.f, 0.f, 0.f, 0.f);
        float den0 = 0.f, den2 = 0.f;
        edge_loop(g_sid[0] + g_off[0][d], g_deg[0][d], g_Pa_h,       640, qv,
                  rel_pri[h] * 0.25f, lane, a0, den0);
        edge_loop(g_sid[2] + g_off[2][d], g_deg[2][d], g_Pa_h + 256, 640, qv,
                  rel_pri[2 * HH + h] * 0.25f, lane, a2, den2);
        float s0 = (den0 > 0.f) ? (0.5f / den0) : 0.f;
        float s2 = (den2 > 0.f) ? (0.5f / den2) : 0.f;
        outv = make_float4(a0.x * s0 + a2.x * s2, a0.y * s0 + a2.y * s2,
                           a0.z * s0 + a2.z * s2, a0.w * s0 + a2.w * s2);
    }
    __half2 o01 = __floats2half2_rn(outv.x, outv.y);
    __half2 o23 = __floats2half2_rn(outv.z, outv.w);
    *(uint2*)(g_t_h[grp] + (size_t)d * D + lane * 4) =
        make_uint2(*(uint32_t*)&o01, *(uint32_t*)&o23);
}

// ===================== single-pass fp16 GEMM (proj + out) ===================
#define PAS 68                                    // words per row (conflict-free)
#define P_AS_WORDS (128 * PAS)                    // 8704
#define P_BS_WORDS (64 * PAS)                     // 4352
#define P_SMEM_BYTES ((P_AS_WORDS + P_BS_WORDS) * 4)   // 52224

// mode 0 (proj): by 0/1 -> Pa tiles 0-4/5-9 (A=ha fp32); by 2 -> Pb tiles 0-5.
// mode 1 (out):  by=which, A = g_t_h[by] (fp16 direct), fp32 out + skip-mix.
__global__ void __launch_bounds__(256) gemm_f16(
    int mode, const float* __restrict__ ha, const float* __restrict__ hb,
    const float* __restrict__ skipv, float* __restrict__ out)
{
    extern __shared__ uint32_t sm[];
    uint32_t* As = sm;
    uint32_t* Bs = sm + P_AS_WORDS;
    int by = blockIdx.y;
    const float* Af32 = nullptr;
    const __half* Af16 = nullptr;
    int wtRow, cStride, nt0, nNT;
    __half* Ch = nullptr;
    float* Cf = nullptr;
    const float* resid = nullptr;
    if (mode == 0) {
        if (by == 0)      { Af32 = ha; wtRow = 0;   Ch = g_Pa_h; cStride = 640; nt0 = 0; nNT = 5; }
        else if (by == 1) { Af32 = ha; wtRow = 0;   Ch = g_Pa_h; cStride = 640; nt0 = 5; nNT = 5; }
        else              { Af32 = hb; wtRow = 640; Ch = g_Pb_h; cStride = 384; nt0 = 0; nNT = 6; }
    } else {
        Af16 = g_t_h[by]; wtRow = 1024 + by * 128; Cf = out + (size_t)by * NN * D;
        cStride = 128; nt0 = 0; nNT = 2;
        resid = by ? hb : ha;
    }
    int biasOff = wtRow;

    int tid = threadIdx.x, lane = tid & 31, wid = tid >> 5;
    int warp_m = wid >> 1, warp_n = wid & 1;
    int g = lane >> 2, tg = lane & 3;
    int m0 = blockIdx.x * 128;
    const int M = NN;

    // ---- load A tile once ----
    if (Af32) {
        #pragma unroll
        for (int u = 0; u < 16; u++) {
            int flat = u * 256 + tid;          // 0..4095 float4 slots
            int row = flat >> 5, part = flat & 31;
            int grow = m0 + row;
            float4 v = make_float4(0.f, 0.f, 0.f, 0.f);
            if (grow < M) v = *(const float4*)(Af32 + ((size_t)grow << 7) + part * 4);
            __half2 h01 = __floats2half2_rn(v.x, v.y);
            __half2 h23 = __floats2half2_rn(v.z, v.w);
            *(uint2*)&As[row * PAS + part * 2] =
                make_uint2(*(uint32_t*)&h01, *(uint32_t*)&h23);
        }
    } else {
        #pragma unroll
        for (int u = 0; u < 8; u++) {
            int flat = u * 256 + tid;          // 0..2047 uint4 slots (8 halves)
            int row = flat >> 4, part = flat & 15;
            int grow = m0 + row;
            uint4 v = make_uint4(0u, 0u, 0u, 0u);
            if (grow < M) v = *(const uint4*)(Af16 + ((size_t)grow << 7) + part * 8);
            *(uint4*)&As[row * PAS + part * 4] = v;
        }
    }
    __syncthreads();

    float alpha = 1.f, om = 0.f;
    if (resid) {
        float s = skipv[by];
        alpha = 1.f / (1.f + expf(-s));
        om = 1.f - alpha;
    }

    for (int nt = nt0; nt < nt0 + nNT; nt++) {
        int n0 = nt * 64;
        // ---- load B tile (fp16, L2-resident) ----
        #pragma unroll
        for (int u = 0; u < 4; u++) {
            int flat = u * 256 + tid;          // 0..1023 uint4 slots
            int row = flat >> 4, part = flat & 15;
            const __half* src = g_Wt16 + (size_t)(wtRow + n0 + row) * D + part * 8;
            *(uint4*)&Bs[row * PAS + part * 4] = *(const uint4*)src;
        }
        __syncthreads();

        float acc[2][4][4];
        #pragma unroll
        for (int mt = 0; mt < 2; mt++)
            #pragma unroll
            for (int ntt = 0; ntt < 4; ntt++)
                #pragma unroll
                for (int i = 0; i < 4; i++) acc[mt][ntt][i] = 0.f;

        #pragma unroll
        for (int kk = 0; kk < 8; kk++) {
            int kp0 = kk * 8;
            uint32_t a[2][4], b[4][2];
            #pragma unroll
            for (int mt = 0; mt < 2; mt++) {
                int rb = warp_m * 32 + mt * 16;
                a[mt][0] = As[(rb + g) * PAS + kp0 + tg];
                a[mt][1] = As[(rb + g + 8) * PAS + kp0 + tg];
                a[mt][2] = As[(rb + g) * PAS + kp0 + tg + 4];
                a[mt][3] = As[(rb + g + 8) * PAS + kp0 + tg + 4];
            }
            #pragma unroll
            for (int ntt = 0; ntt < 4; ntt++) {
                int cb = warp_n * 32 + ntt * 8;
                b[ntt][0] = Bs[(cb + g) * PAS + kp0 + tg];
                b[ntt][1] = Bs[(cb + g) * PAS + kp0 + tg + 4];
            }
            #pragma unroll
            for (int mt = 0; mt < 2; mt++)
                #pragma unroll
                for (int ntt = 0; ntt < 4; ntt++)
                    mma_f16(acc[mt][ntt], a[mt], b[ntt]);
        }
        __syncthreads();

        // ---- epilogue ----
        #pragma unroll
        for (int mt = 0; mt < 2; mt++)
            #pragma unroll
            for (int ntt = 0; ntt < 4; ntt++) {
                int col = n0 + warp_n * 32 + ntt * 8 + tg * 2;
                float b0 = g_bias[biasOff + col], b1 = g_bias[biasOff + col + 1];
                #pragma unroll
                for (int half = 0; half < 2; half++) {
                    int row = m0 + warp_m * 32 + mt * 16 + g + half * 8;
                    if (row >= M) continue;
                    float v0 = acc[mt][ntt][half * 2 + 0] + b0;
                    float v1 = acc[mt][ntt][half * 2 + 1] + b1;
                    if (mode == 0) {
                        *(__half2*)(Ch + (size_t)row * cStride + col) = __floats2half2_rn(v0, v1);
                    } else {
                        v0 = v0 * alpha + resid[(size_t)row * D + col] * om;
                        v1 = v1 * alpha + resid[(size_t)row * D + col + 1] * om;
                        *(float2*)(Cf + (size_t)row * cStride + col) = make_float2(v0, v1);
                    }
                }
            }
    }
}

// ---------------- launch ----------------------------------------------------
extern "C" void kernel_launch(void* const* d_in, const int* in_sizes, int n_in,
                              void* d_out, int out_size) {
    const float* h_a = (const float*)d_in[0];
    const float* h_b = (const float*)d_in[1];
    const int* src0 = (const int*)d_in[2]; const int* dst0 = (const int*)d_in[3];
    const int* src1 = (const int*)d_in[4]; const int* dst1 = (const int*)d_in[5];
    const int* src2 = (const int*)d_in[6]; const int* dst2 = (const int*)d_in[7];
    const float* Wk = (const float*)d_in[8];  const float* bk = (const float*)d_in[9];
    const float* Wv = (const float*)d_in[10]; const float* bv = (const float*)d_in[11];
    const float* Wq = (const float*)d_in[12]; const float* bq = (const float*)d_in[13];
    const float* Wa = (const float*)d_in[14]; const float* ba = (const float*)d_in[15];
    const float* rel_att = (const float*)d_in[16];
    const float* rel_msg = (const float*)d_in[17];
    const float* rel_pri = (const float*)d_in[18];
    const float* skip    = (const float*)d_in[19];
    float* out = (float*)d_out;

    static cudaStream_t s2 = nullptr;
    static cudaEvent_t evFork = nullptr, evJoin = nullptr;
    if (s2 == nullptr) {
        cudaStreamCreateWithFlags(&s2, cudaStreamNonBlocking);
        cudaEventCreateWithFlags(&evFork, cudaEventDisableTiming);
        cudaEventCreateWithFlags(&evJoin, cudaEventDisableTiming);
    }

    cudaFuncSetAttribute(gemm_f16, cudaFuncAttributeMaxDynamicSharedMemorySize, P_SMEM_BYTES);

    // fork: CSR build on side stream, overlapped with weight prep + proj GEMM
    cudaEventRecord(evFork, 0);
    cudaStreamWaitEvent(s2, evFork, 0);
    zero_kernel<<<(3 * NN + 255) / 256, 256, 0, s2>>>();
    hist_kernel<<<(3 * EE + 255) / 256, 256, 0, s2>>>(dst0, dst1, dst2);
    scan_kernel<<<dim3((NN + 1023) / 1024, 3), 1024, 0, s2>>>();
    fill_kernel<<<(3 * EE + 255) / 256, 256, 0, s2>>>(src0, dst0, src1, dst1, src2, dst2);
    cudaEventRecord(evJoin, s2);

    // main stream: weights + projections (single-pass fp16)
    wcat_kernel<<<(WT_ROWS * D + 255) / 256, 256>>>(Wk, bk, Wv, bv, Wq, bq, Wa, ba, rel_att, rel_msg);
    int gm = (NN + 127) / 128;   // 782
    gemm_f16<<<dim3(gm, 3), 256, P_SMEM_BYTES>>>(0, h_a, h_b, skip, out);

    // join: aggregation needs projections + CSR
    cudaStreamWaitEvent(0, evJoin, 0);
    aggr_kernel<<<(2 * NN * 32 + 255) / 256, 256>>>(rel_pri);

    // output projections (single-pass fp16) with skip mixing
    gemm_f16<<<dim3(gm, 2), 256, P_SMEM_BYTES>>>(1, h_a, h_b, skip, out);
}

// round 17
// speedup vs baseline: 1.3970x; 1.0271x over previous
#include <cuda_runtime.h>
#include <cuda_bf16.h>
#include <cuda_fp16.h>
#include <math.h>
#include <stdint.h>

#define NN 100000
#define EE 500000
#define D  128
#define HH 8
#define DKH 16

// ===================== scratch ==============================================
__device__ __half g_Pa_h[(size_t)NN * 640];   // [K_r0 | V_r0 | K_r2 | V_r2 | Q_a]
__device__ __half g_Pb_h[(size_t)NN * 384];   // [K_r1 | V_r1 | Q_b]
__device__ __half g_t_h[2][(size_t)NN * D];   // 0: t_a (rel1), 1: t_b (rel0+2, normalized)
#define WT_ROWS (640 + 384 + 128 + 128)       // 1280 (all fp16)
__device__ __half g_Wt16[WT_ROWS * D];        // W^T in fp16
__device__ float g_bias[WT_ROWS];
// CSR scratch
__device__ int g_deg[3][NN];
__device__ int g_off[3][NN];
__device__ int g_cur[3][NN];
__device__ int g_sid[3][EE];
__device__ int g_base[3];

// ---------------- helpers ----------------------------------------------------
__device__ __forceinline__ void mma_f16(float* c, const uint32_t* a, const uint32_t* b) {
    asm volatile("mma.sync.aligned.m16n8k16.row.col.f32.f16.f16.f32 "
                 "{%0,%1,%2,%3},{%4,%5,%6,%7},{%8,%9},{%0,%1,%2,%3};"
                 : "+f"(c[0]), "+f"(c[1]), "+f"(c[2]), "+f"(c[3])
                 : "r"(a[0]), "r"(a[1]), "r"(a[2]), "r"(a[3]), "r"(b[0]), "r"(b[1]));
}
__device__ __forceinline__ void loadf8(const __half* p, float* f) {
    uint4 q = *(const uint4*)p;
    const __half2* h = (const __half2*)&q;
    #pragma unroll
    for (int j = 0; j < 4; j++) {
        float2 t = __half22float2(h[j]);
        f[j * 2 + 0] = t.x;
        f[j * 2 + 1] = t.y;
    }
}

// ---------------- zero CSR counters each launch ------------------------------
__global__ void zero_kernel() {
    int idx = blockIdx.x * blockDim.x + threadIdx.x;
    int* dp = &g_deg[0][0];
    if (idx < 3 * NN) dp[idx] = 0;
    if (idx < 3) g_base[idx] = 0;
}

// ---------------- build transposed, relation-folded fp16 weights -------------
__global__ void wcat_kernel(const float* __restrict__ Wk, const float* __restrict__ bk,
                            const float* __restrict__ Wv, const float* __restrict__ bv,
                            const float* __restrict__ Wq, const float* __restrict__ bq,
                            const float* __restrict__ Wa, const float* __restrict__ ba,
                            const float* __restrict__ rel_att, const float* __restrict__ rel_msg) {
    int idx = blockIdx.x * blockDim.x + threadIdx.x;
    if (idx >= WT_ROWS * D) return;
    int u = idx / D;      // output column n (transposed row)
    int k = idx % D;      // input dim
    float val = 0.f, bval = 0.f;
    if (u >= 1024) {      // out-proj GEMMs: plain Wa transpose
        int which = (u >= 1152) ? 1 : 0;
        int n = u - 1024 - which * 128;
        val  = Wa[which * D * D + k * D + n];
        bval = ba[which * D + n];
    } else {
        int o, tsrc;
        if (u < 640) { o = u;       tsrc = 0; }
        else         { o = u - 640; tsrc = 1; }
        int seg = o >> 7, oo = o & 127;
        bool isQ = (tsrc == 0) ? (seg == 4) : (seg == 2);
        if (isQ) {
            val  = Wq[tsrc * D * D + k * D + oo];
            bval = bq[tsrc * D + oo];
        } else {
            int r; bool isV;
            if (tsrc == 0) { r = (seg < 2) ? 0 : 2; isV = (seg & 1); }
            else           { r = 1; isV = (seg == 1); }
            const float* Wm  = isV ? Wv : Wk;
            const float* bm  = isV ? bv : bk;
            const float* rel = isV ? rel_msg : rel_att;
            int h = oo >> 4, e = oo & 15;
            const float* wrow = Wm + tsrc * D * D + k * D + h * DKH;
            const float* brow = bm + tsrc * D + h * DKH;
            const float* relm = rel + (r * HH + h) * DKH * DKH;
            float s = 0.f, sb = 0.f;
            #pragma unroll
            for (int d2 = 0; d2 < DKH; d2++) {
                float rv = relm[d2 * DKH + e];
                s  += wrow[d2] * rv;
                sb += brow[d2] * rv;
            }
            val = s; bval = sb;
        }
    }
    g_Wt16[u * D + k] = __float2half(val);
    if (k == 0) g_bias[u] = bval;
}

// ===================== CSR build ============================================
__global__ void hist_kernel(const int* __restrict__ d0, const int* __restrict__ d1,
                            const int* __restrict__ d2) {
    int idx = blockIdx.x * blockDim.x + threadIdx.x;
    if (idx >= 3 * EE) return;
    int r = idx / EE, e = idx - r * EE;
    const int* dp = (r == 0) ? d0 : (r == 1) ? d1 : d2;
    atomicAdd(&g_deg[r][dp[e]], 1);
}

__global__ void scan_kernel() {   // grid (98, 3), block 1024
    __shared__ int sh[1024];
    __shared__ int sbase;
    int r = blockIdx.y, tid = threadIdx.x;
    int i = blockIdx.x * 1024 + tid;
    int v = (i < NN) ? g_deg[r][i] : 0;
    sh[tid] = v;
    __syncthreads();
    for (int s = 1; s < 1024; s <<= 1) {
        int t = (tid >= s) ? sh[tid - s] : 0;
        __syncthreads();
        sh[tid] += t;
        __syncthreads();
    }
    if (tid == 1023) sbase = atomicAdd(&g_base[r], sh[1023]);
    __syncthreads();
    int off = sbase + sh[tid] - v;
    if (i < NN) { g_off[r][i] = off; g_cur[r][i] = off; }
}

__global__ void fill_kernel(const int* __restrict__ s0, const int* __restrict__ d0,
                            const int* __restrict__ s1, const int* __restrict__ d1,
                            const int* __restrict__ s2, const int* __restrict__ d2) {
    int idx = blockIdx.x * blockDim.x + threadIdx.x;
    if (idx >= 3 * EE) return;
    int r = idx / EE, e = idx - r * EE;
    const int* sp = (r == 0) ? s0 : (r == 1) ? s1 : s2;
    const int* dp = (r == 0) ? d0 : (r == 1) ? d1 : d2;
    int pos = atomicAdd(&g_cur[r][dp[e]], 1);
    g_sid[r][pos] = sp[e];
}

// ===================== dst-major edge aggregation (2 edges x 16 lanes) ======
// Each 16-lane group processes one edge; lane owns 8 channels (one uint4 for
// k, one for v). Lane pair (2j,2j+1) covers head j -> dot reduce = 1 shfl.
// Invalid slots are predicated off (no extra traffic). Combine groups once.
__device__ __forceinline__ void edge_loop2(const int* __restrict__ sp, int deg,
    const __half* __restrict__ base, int stride, const float* q8, float pri,
    int lane, float* acc8, float& den)
{
    int eg = lane >> 4;        // edge group 0/1
    int sub = lane & 15;       // channel block: sub*8
    for (int i0 = 0; i0 < deg; i0 += 32) {
        int nb = deg - i0; if (nb > 32) nb = 32;
        int sid = (lane < nb) ? sp[i0 + lane] : 0;
        for (int i = 0; i < nb; i += 2) {
            int idx = i + eg;
            bool valid = idx < nb;
            int s = __shfl_sync(0xffffffffu, sid, idx & 31);
            float k8[8], v8[8];
            if (valid) {
                const __half* row = base + (size_t)s * stride + sub * 8;
                loadf8(row, k8);
                loadf8(row + 128, v8);
            } else {
                #pragma unroll
                for (int j = 0; j < 8; j++) { k8[j] = 0.f; v8[j] = 0.f; }
            }
            float dot = 0.f;
            #pragma unroll
            for (int j = 0; j < 8; j++) dot += k8[j] * q8[j];
            dot += __shfl_xor_sync(0xffffffffu, dot, 1);
            float ex = valid ? __expf(dot * pri) : 0.f;
            #pragma unroll
            for (int j = 0; j < 8; j++) acc8[j] += v8[j] * ex;
            den += ex;
        }
    }
    // combine the two edge groups
    #pragma unroll
    for (int j = 0; j < 8; j++)
        acc8[j] += __shfl_xor_sync(0xffffffffu, acc8[j], 16);
    den += __shfl_xor_sync(0xffffffffu, den, 16);
}

// one warp per (group, dst). group 0: rel1 -> t_a. group 1: rel0+rel2 -> t_b
__global__ void aggr_kernel(const float* __restrict__ rel_pri) {
    int gw = (blockIdx.x * blockDim.x + threadIdx.x) >> 5;
    if (gw >= 2 * NN) return;
    int grp = gw / NN, d = gw - grp * NN;
    int lane = threadIdx.x & 31, sub = lane & 15;
    int h = sub >> 1;          // head owned by this lane's channel block

    float q8[8], out8[8];
    if (grp == 0) {
        loadf8(g_Pa_h + (size_t)d * 640 + 512 + sub * 8, q8);
        float acc[8] = {};
        float den = 0.f;
        edge_loop2(g_sid[1] + g_off[1][d], g_deg[1][d], g_Pb_h, 384, q8,
                   rel_pri[HH + h] * 0.25f, lane, acc, den);
        float dn = (den > 0.f) ? (1.f / den) : 0.f;
        #pragma unroll
        for (int j = 0; j < 8; j++) out8[j] = acc[j] * dn;
    } else {
        loadf8(g_Pb_h + (size_t)d * 384 + 256 + sub * 8, q8);
        float acc[8] = {};
        float den = 0.f;
        edge_loop2(g_sid[0] + g_off[0][d], g_deg[0][d], g_Pa_h, 640, q8,
                   rel_pri[h] * 0.25f, lane, acc, den);
        float s0 = (den > 0.f) ? (0.5f / den) : 0.f;
        #pragma unroll
        for (int j = 0; j < 8; j++) { out8[j] = acc[j] * s0; acc[j] = 0.f; }
        den = 0.f;
        edge_loop2(g_sid[2] + g_off[2][d], g_deg[2][d], g_Pa_h + 256, 640, q8,
                   rel_pri[2 * HH + h] * 0.25f, lane, acc, den);
        float s2 = (den > 0.f) ? (0.5f / den) : 0.f;
        #pragma unroll
        for (int j = 0; j < 8; j++) out8[j] += acc[j] * s2;
    }
    if (lane < 16) {
        __half2 o[4];
        #pragma unroll
        for (int j = 0; j < 4; j++)
            o[j] = __floats2half2_rn(out8[j * 2], out8[j * 2 + 1]);
        *(uint4*)(g_t_h[grp] + (size_t)d * D + sub * 8) = *(uint4*)o;
    }
}

// ===================== single-pass fp16 GEMM (proj + out) ===================
#define PAS 68                                    // words per row (conflict-free)
#define P_AS_WORDS (128 * PAS)                    // 8704
#define P_BS_WORDS (64 * PAS)                     // 4352
#define P_SMEM_BYTES ((P_AS_WORDS + P_BS_WORDS) * 4)   // 52224

// mode 0 (proj): by 0/1 -> Pa tiles 0-4/5-9 (A=ha fp32); by 2 -> Pb tiles 0-5.
// mode 1 (out):  by=which, A = g_t_h[by] (fp16 direct), fp32 out + skip-mix.
__global__ void __launch_bounds__(256) gemm_f16(
    int mode, const float* __restrict__ ha, const float* __restrict__ hb,
    const float* __restrict__ skipv, float* __restrict__ out)
{
    extern __shared__ uint32_t sm[];
    uint32_t* As = sm;
    uint32_t* Bs = sm + P_AS_WORDS;
    int by = blockIdx.y;
    const float* Af32 = nullptr;
    const __half* Af16 = nullptr;
    int wtRow, cStride, nt0, nNT;
    __half* Ch = nullptr;
    float* Cf = nullptr;
    const float* resid = nullptr;
    if (mode == 0) {
        if (by == 0)      { Af32 = ha; wtRow = 0;   Ch = g_Pa_h; cStride = 640; nt0 = 0; nNT = 5; }
        else if (by == 1) { Af32 = ha; wtRow = 0;   Ch = g_Pa_h; cStride = 640; nt0 = 5; nNT = 5; }
        else              { Af32 = hb; wtRow = 640; Ch = g_Pb_h; cStride = 384; nt0 = 0; nNT = 6; }
    } else {
        Af16 = g_t_h[by]; wtRow = 1024 + by * 128; Cf = out + (size_t)by * NN * D;
        cStride = 128; nt0 = 0; nNT = 2;
        resid = by ? hb : ha;
    }
    int biasOff = wtRow;

    int tid = threadIdx.x, lane = tid & 31, wid = tid >> 5;
    int warp_m = wid >> 1, warp_n = wid & 1;
    int g = lane >> 2, tg = lane & 3;
    int m0 = blockIdx.x * 128;
    const int M = NN;

    // ---- load A tile once ----
    if (Af32) {
        #pragma unroll
        for (int u = 0; u < 16; u++) {
            int flat = u * 256 + tid;          // 0..4095 float4 slots
            int row = flat >> 5, part = flat & 31;
            int grow = m0 + row;
            float4 v = make_float4(0.f, 0.f, 0.f, 0.f);
            if (grow < M) v = *(const float4*)(Af32 + ((size_t)grow << 7) + part * 4);
            __half2 h01 = __floats2half2_rn(v.x, v.y);
            __half2 h23 = __floats2half2_rn(v.z, v.w);
            *(uint2*)&As[row * PAS + part * 2] =
                make_uint2(*(uint32_t*)&h01, *(uint32_t*)&h23);
        }
    } else {
        #pragma unroll
        for (int u = 0; u < 8; u++) {
            int flat = u * 256 + tid;          // 0..2047 uint4 slots (8 halves)
            int row = flat >> 4, part = flat & 15;
            int grow = m0 + row;
            uint4 v = make_uint4(0u, 0u, 0u, 0u);
            if (grow < M) v = *(const uint4*)(Af16 + ((size_t)grow << 7) + part * 8);
            *(uint4*)&As[row * PAS + part * 4] = v;
        }
    }
    __syncthreads();

    float alpha = 1.f, om = 0.f;
    if (resid) {
        float s = skipv[by];
        alpha = 1.f / (1.f + expf(-s));
        om = 1.f - alpha;
    }

    for (int nt = nt0; nt < nt0 + nNT; nt++) {
        int n0 = nt * 64;
        // ---- load B tile (fp16, L2-resident) ----
        #pragma unroll
        for (int u = 0; u < 4; u++) {
            int flat = u * 256 + tid;          // 0..1023 uint4 slots
            int row = flat >> 4, part = flat & 15;
            const __half* src = g_Wt16 + (size_t)(wtRow + n0 + row) * D + part * 8;
            *(uint4*)&Bs[row * PAS + part * 4] = *(const uint4*)src;
        }
        __syncthreads();

        float acc[2][4][4];
        #pragma unroll
        for (int mt = 0; mt < 2; mt++)
            #pragma unroll
            for (int ntt = 0; ntt < 4; ntt++)
                #pragma unroll
                for (int i = 0; i < 4; i++) acc[mt][ntt][i] = 0.f;

        #pragma unroll
        for (int kk = 0; kk < 8; kk++) {
            int kp0 = kk * 8;
            uint32_t a[2][4], b[4][2];
            #pragma unroll
            for (int mt = 0; mt < 2; mt++) {
                int rb = warp_m * 32 + mt * 16;
                a[mt][0] = As[(rb + g) * PAS + kp0 + tg];
                a[mt][1] = As[(rb + g + 8) * PAS + kp0 + tg];
                a[mt][2] = As[(rb + g) * PAS + kp0 + tg + 4];
                a[mt][3] = As[(rb + g + 8) * PAS + kp0 + tg + 4];
            }
            #pragma unroll
            for (int ntt = 0; ntt < 4; ntt++) {
                int cb = warp_n * 32 + ntt * 8;
                b[ntt][0] = Bs[(cb + g) * PAS + kp0 + tg];
                b[ntt][1] = Bs[(cb + g) * PAS + kp0 + tg + 4];
            }
            #pragma unroll
            for (int mt = 0; mt < 2; mt++)
                #pragma unroll
                for (int ntt = 0; ntt < 4; ntt++)
                    mma_f16(acc[mt][ntt], a[mt], b[ntt]);
        }
        __syncthreads();

        // ---- epilogue ----
        #pragma unroll
        for (int mt = 0; mt < 2; mt++)
            #pragma unroll
            for (int ntt = 0; ntt < 4; ntt++) {
                int col = n0 + warp_n * 32 + ntt * 8 + tg * 2;
                float b0 = g_bias[biasOff + col], b1 = g_bias[biasOff + col + 1];
                #pragma unroll
                for (int half = 0; half < 2; half++) {
                    int row = m0 + warp_m * 32 + mt * 16 + g + half * 8;
                    if (row >= M) continue;
                    float v0 = acc[mt][ntt][half * 2 + 0] + b0;
                    float v1 = acc[mt][ntt][half * 2 + 1] + b1;
                    if (mode == 0) {
                        *(__half2*)(Ch + (size_t)row * cStride + col) = __floats2half2_rn(v0, v1);
                    } else {
                        v0 = v0 * alpha + resid[(size_t)row * D + col] * om;
                        v1 = v1 * alpha + resid[(size_t)row * D + col + 1] * om;
                        *(float2*)(Cf + (size_t)row * cStride + col) = make_float2(v0, v1);
                    }
                }
            }
    }
}

// ---------------- launch ----------------------------------------------------
extern "C" void kernel_launch(void* const* d_in, const int* in_sizes, int n_in,
                              void* d_out, int out_size) {
    const float* h_a = (const float*)d_in[0];
    const float* h_b = (const float*)d_in[1];
    const int* src0 = (const int*)d_in[2]; const int* dst0 = (const int*)d_in[3];
    const int* src1 = (const int*)d_in[4]; const int* dst1 = (const int*)d_in[5];
    const int* src2 = (const int*)d_in[6]; const int* dst2 = (const int*)d_in[7];
    const float* Wk = (const float*)d_in[8];  const float* bk = (const float*)d_in[9];
    const float* Wv = (const float*)d_in[10]; const float* bv = (const float*)d_in[11];
    const float* Wq = (const float*)d_in[12]; const float* bq = (const float*)d_in[13];
    const float* Wa = (const float*)d_in[14]; const float* ba = (const float*)d_in[15];
    const float* rel_att = (const float*)d_in[16];
    const float* rel_msg = (const float*)d_in[17];
    const float* rel_pri = (const float*)d_in[18];
    const float* skip    = (const float*)d_in[19];
    float* out = (float*)d_out;

    static cudaStream_t s2 = nullptr;
    static cudaEvent_t evFork = nullptr, evJoin = nullptr;
    if (s2 == nullptr) {
        cudaStreamCreateWithFlags(&s2, cudaStreamNonBlocking);
        cudaEventCreateWithFlags(&evFork, cudaEventDisableTiming);
        cudaEventCreateWithFlags(&evJoin, cudaEventDisableTiming);
    }

    cudaFuncSetAttribute(gemm_f16, cudaFuncAttributeMaxDynamicSharedMemorySize, P_SMEM_BYTES);

    // fork: CSR build on side stream, overlapped with weight prep + proj GEMM
    cudaEventRecord(evFork, 0);
    cudaStreamWaitEvent(s2, evFork, 0);
    zero_kernel<<<(3 * NN + 255) / 256, 256, 0, s2>>>();
    hist_kernel<<<(3 * EE + 255) / 256, 256, 0, s2>>>(dst0, dst1, dst2);
    scan_kernel<<<dim3((NN + 1023) / 1024, 3), 1024, 0, s2>>>();
    fill_kernel<<<(3 * EE + 255) / 256, 256, 0, s2>>>(src0, dst0, src1, dst1, src2, dst2);
    cudaEventRecord(evJoin, s2);

    // main stream: weights + projections (single-pass fp16)
    wcat_kernel<<<(WT_ROWS * D + 255) / 256, 256>>>(Wk, bk, Wv, bv, Wq, bq, Wa, ba, rel_att, rel_msg);
    int gm = (NN + 127) / 128;   // 782
    gemm_f16<<<dim3(gm, 3), 256, P_SMEM_BYTES>>>(0, h_a, h_b, skip, out);

    // join: aggregation needs projections + CSR
    cudaStreamWaitEvent(0, evJoin, 0);
    aggr_kernel<<<(2 * NN * 32 + 255) / 256, 256>>>(rel_pri);

    // output projections (single-pass fp16) with skip mixing
    gemm_f16<<<dim3(gm, 2), 256, P_SMEM_BYTES>>>(1, h_a, h_b, skip, out);
}